// round 7
// baseline (speedup 1.0000x reference)
#include <cuda_runtime.h>
#include <cuda_fp16.h>
#include <math.h>

// ---------------- problem dims ----------------
#define BB    64
#define NN    1024
#define H16   256
#define H64   1024
#define H128  2048
#define NGATE 8192

#define NCTA_MAX 148
#define USM 13                                   // units whose fp16 weights live in SMEM
// dynamic SMEM layout for lstm kernel
#define WSM_BYTES (USM * 4 * 2048 * 2)           // 212992
#define OFF_H32   (WSM_BYTES)                    // fp32 h copy   (8192 B)
#define OFF_H16   (OFF_H32 + H128 * 4)           // fp16 h copy   (4096 B)
#define OFF_G     (OFF_H16 + H128 * 2)           // gate preacts  (256 B)
#define OFF_C     (OFF_G + 64 * 4)               // cell state    (64 B)
#define LSTM_SMEM (OFF_C + 64)                   // 225664 B

// ---------------- device scratch ----------------
__device__ __align__(16) float g_x [BB * NN];
__device__ __align__(16) float g_af[BB * H16];
__device__ __align__(16) float g_ai[BB * H64];
__device__ __align__(16) float g_z [BB * H128];
__device__ __align__(16) float g_gi[BB * NGATE];
__device__ __align__(16) float g_part[1 << 21];      // split-K partials (8MB)
__device__ __align__(16) float g_h [2][H128];
__device__ unsigned g_slot [NCTA_MAX * 8];           // lstm barrier slots (32B apart)
__device__ unsigned g_slot2[NCTA_MAX * 8];           // mlp barrier slots

__global__ void reset_kernel() {
    for (int i = threadIdx.x; i < NCTA_MAX * 8; i += blockDim.x) {
        g_slot[i] = 0u; g_slot2[i] = 0u;
    }
}

// ---------------- release/acquire helpers ----------------
__device__ __forceinline__ void st_release(unsigned* p, unsigned v) {
    asm volatile("st.release.gpu.global.u32 [%0], %1;" :: "l"(p), "r"(v) : "memory");
}
__device__ __forceinline__ unsigned ld_acquire(const unsigned* p) {
    unsigned v;
    asm volatile("ld.acquire.gpu.global.u32 %0, [%1];" : "=r"(v) : "l"(p) : "memory");
    return v;
}

// spread-slot grid barrier (single wave): arrive via release store, watch via acquire loads
__device__ __forceinline__ void grid_bar(unsigned* slots, int ncta, unsigned& gen)
{
    __syncthreads();
    unsigned tgt = ++gen;
    if (threadIdx.x == 0) st_release(&slots[blockIdx.x * 8], tgt);
    if ((int)threadIdx.x < ncta) { while (ld_acquire(&slots[threadIdx.x * 8]) < tgt) {} }
    __syncthreads();
}

// ---------------- GCN: one block per sample ----------------
__global__ __launch_bounds__(1024) void gcn_kernel(
    const float* __restrict__ inp,
    const float* __restrict__ gc1w, const float* __restrict__ gc1b,
    const float* __restrict__ gc2w, const float* __restrict__ gc2b)
{
    __shared__ float xs[NN];
    __shared__ float s2[NN];
    const int s = blockIdx.x;
    const int i = threadIdx.x;
    xs[i] = inp[s * NN + i];
    __syncthreads();
    const float xi = xs[i];

    float d0 = INFINITY, d1 = INFINITY, d2 = INFINITY, d3 = INFINITY;
    int i0 = 0, i1 = 0, i2 = 0, i3 = 0;
#pragma unroll 4
    for (int j = 0; j < NN; ++j) {
        float dj = fabsf(xi - xs[j]);
        if (j != i && dj < d3) {
            if (dj < d2) {
                d3 = d2; i3 = i2;
                if (dj < d1) {
                    d2 = d1; i2 = i1;
                    if (dj < d0) { d1 = d0; i1 = i0; d0 = dj; i0 = j; }
                    else         { d1 = dj; i1 = j; }
                } else { d2 = dj; i2 = j; }
            } else { d3 = dj; i3 = j; }
        }
    }

    float S = xs[i0] + xs[i1] + xs[i2] + xs[i3];
    float v = 0.f;
#pragma unroll
    for (int c = 0; c < 4; ++c) {
        float hc = fmaxf(gc1w[c] * S + gc1b[c], 0.f);
        v += hc * gc2w[c];
    }
    s2[i] = v;
    __syncthreads();
    g_x[s * NN + i] = s2[i0] + s2[i1] + s2[i2] + s2[i3] + gc2b[0];
}

// ---------------- fused MLP: persistent, double-buffered 64x64 tiles ----------------
template <int R, int J, int KC>
__device__ __forceinline__ void gemm_tiles(
    const float* __restrict__ A, const float* __restrict__ W, float* __restrict__ part,
    int bid, int ncta, float (&As)[2][64][33], float (&Ws)[2][64][33])
{
    const int JC = J / KC;
    const int RT = R / 64;
    const int tid = threadIdx.x;
    const int tq = tid & 15;
    const int rq = tid >> 4;
    const int nit = JC / 32;

    for (int tile = bid; tile < RT * KC; tile += ncta) {
        const int rt = tile % RT, kc = tile / RT;
        const int br0 = rt * 64;
        const int jbeg = kc * JC;

        float acc[4][4];
#pragma unroll
        for (int a = 0; a < 4; ++a)
#pragma unroll
            for (int b = 0; b < 4; ++b) acc[a][b] = 0.f;

        auto load = [&](int s, int j0) {
#pragma unroll
            for (int idx = tid; idx < 64 * 32; idx += 256) {
                int row = idx >> 5, col = idx & 31;
                As[s][row][col] = A[row * J + j0 + col];
                Ws[s][row][col] = W[(size_t)(br0 + row) * J + j0 + col];
            }
        };

        load(0, jbeg);
        __syncthreads();
        for (int it = 0; it < nit; ++it) {
            int s = it & 1;
            if (it + 1 < nit) load(s ^ 1, jbeg + (it + 1) * 32);
#pragma unroll
            for (int kk = 0; kk < 32; ++kk) {
                float av[4], wv[4];
#pragma unroll
                for (int a = 0; a < 4; ++a) av[a] = As[s][tq + 16 * a][kk];
#pragma unroll
                for (int b = 0; b < 4; ++b) wv[b] = Ws[s][rq + 16 * b][kk];
#pragma unroll
                for (int a = 0; a < 4; ++a)
#pragma unroll
                    for (int b = 0; b < 4; ++b) acc[a][b] += av[a] * wv[b];
            }
            __syncthreads();
        }
#pragma unroll
        for (int a = 0; a < 4; ++a)
#pragma unroll
            for (int b = 0; b < 4; ++b)
                part[(size_t)kc * 64 * R + (tq + 16 * a) * R + br0 + rq + 16 * b] = acc[a][b];
    }
}

template <int R, int KC, bool RELU, bool HASB2>
__device__ __forceinline__ void reduce_layer(
    const float* __restrict__ part, const float* __restrict__ b1,
    const float* __restrict__ b2, float* __restrict__ C, int bid, int ncta)
{
    for (int i = bid * 256 + threadIdx.x; i < 64 * R; i += ncta * 256) {
        int r = i % R;
        float s = 0.f;
#pragma unroll
        for (int kc = 0; kc < KC; ++kc) s += part[(size_t)kc * 64 * R + i];
        s += b1[r];
        if (HASB2) s += b2[r];
        if (RELU) s = fmaxf(s, 0.f);
        C[i] = s;
    }
}

__global__ __launch_bounds__(256, 1) void mlp_kernel(
    const float* __restrict__ flw, const float* __restrict__ flb,
    const float* __restrict__ ilw, const float* __restrict__ ilb,
    const float* __restrict__ olw, const float* __restrict__ olb,
    const float* __restrict__ wih, const float* __restrict__ bih,
    const float* __restrict__ bhh, int ncta)
{
    __shared__ float As[2][64][33];
    __shared__ float Ws[2][64][33];
    const int bid = blockIdx.x;
    unsigned gen = 0;

    // fl: [64,256] = x @ fl_w.T ; relu      (4 tiles x KC32 = 128 tiles)
    gemm_tiles<H16, NN, 32>(g_x, flw, g_part, bid, ncta, As, Ws);
    grid_bar(g_slot2, ncta, gen);
    reduce_layer<H16, 32, true, false>(g_part, flb, nullptr, g_af, bid, ncta);
    grid_bar(g_slot2, ncta, gen);
    // il: [64,1024] = af @ il_w.T ; relu    (16 x KC8 = 128)
    gemm_tiles<H64, H16, 8>(g_af, ilw, g_part, bid, ncta, As, Ws);
    grid_bar(g_slot2, ncta, gen);
    reduce_layer<H64, 8, true, false>(g_part, ilb, nullptr, g_ai, bid, ncta);
    grid_bar(g_slot2, ncta, gen);
    // ol: [64,2048] = ai @ ol_w.T ; relu    (32 x KC4 = 128)
    gemm_tiles<H128, H64, 4>(g_ai, olw, g_part, bid, ncta, As, Ws);
    grid_bar(g_slot2, ncta, gen);
    reduce_layer<H128, 4, true, false>(g_part, olb, nullptr, g_z, bid, ncta);
    grid_bar(g_slot2, ncta, gen);
    // gate: [64,8192] = z @ w_ih.T + b_ih + b_hh   (128 x KC4 = 512)
    gemm_tiles<NGATE, H128, 4>(g_z, wih, g_part, bid, ncta, As, Ws);
    grid_bar(g_slot2, ncta, gen);
    reduce_layer<NGATE, 4, false, true>(g_part, bih, bhh, g_gi, bid, ncta);
}

__device__ __forceinline__ float sigmoidf_(float x) { return 1.f / (1.f + expf(-x)); }

// ---------------- persistent LSTM: SMEM fp16 weights, all warps active ----------------
__global__ __launch_bounds__(1024, 1) void lstm_kernel(
    const float* __restrict__ w_hh, float* __restrict__ out, int ncta)
{
    extern __shared__ unsigned char sm[];
    __half* w_sm = (__half*)sm;                     // [4*usm][2048] fp16
    float*  h32  = (float*)(sm + OFF_H32);          // [2048]
    __half* h16  = (__half*)(sm + OFF_H16);         // [2048]
    float*  gsm  = (float*)(sm + OFF_G);            // [64]
    float*  csm  = (float*)(sm + OFF_C);            // [16]

    const int tid  = threadIdx.x;
    const int bid  = blockIdx.x;
    const int warp = tid >> 5, lane = tid & 31;

    const int base = H128 / ncta;
    const int rem  = H128 - base * ncta;
    const int nu   = (bid < rem) ? base + 1 : base;
    const int u0   = bid * base + min(bid, rem);
    const int usm  = (nu < USM) ? nu : USM;
    const int nrows = 4 * nu;

    // prologue: convert this CTA's SMEM-resident rows fp32 -> fp16 (once per launch)
    {
        const int tot2 = usm * 4 * 1024;
        __half2* dst = (__half2*)w_sm;
        for (int idx = tid; idx < tot2; idx += 1024) {
            int sr = idx >> 10, c2 = idx & 1023;
            int g = sr / usm, ui = sr - g * usm;
            const float2* src = (const float2*)(w_hh + (size_t)(g * H128 + u0 + ui) * H128);
            float2 v = src[c2];
            dst[idx] = __floats2half2_rn(v.x, v.y);
        }
    }

    // per-warp row assignment: lr = warp + 32*k
    int cnt = 0;
    int rowg[2], gsl[2];
    bool insm[2];
    const uint4*  wr16[2];
    const float4* wr32[2];
#pragma unroll
    for (int k = 0; k < 2; ++k) {
        int lr = warp + 32 * k;
        if (lr < nrows) {
            int g = lr / nu, ui = lr - g * nu;
            rowg[cnt] = g * H128 + u0 + ui;
            gsl [cnt] = lr;
            insm[cnt] = (ui < usm);
            wr16[cnt] = (const uint4*)(w_sm + (size_t)(g * usm + ui) * H128);
            wr32[cnt] = (const float4*)(w_hh + (size_t)rowg[cnt] * H128);
            ++cnt;
        }
    }

    if (tid < nu) { csm[tid] = 0.f; g_h[0][u0 + tid] = 0.f; }
    __syncthreads();
    if (tid == 0) st_release(&g_slot[bid * 8], 1u);
    if (tid < ncta) { while (ld_acquire(&g_slot[tid * 8]) < 1u) {} }
    __syncthreads();

    for (int t = 0; t < BB; ++t) {
        // broadcast h into SMEM (fp32 + fp16)
        if (tid < H128 / 4) {
            float4 v = __ldcg(&((const float4*)g_h[t & 1])[tid]);
            ((float4*)h32)[tid] = v;
            ((__half2*)h16)[2 * tid]     = __floats2half2_rn(v.x, v.y);
            ((__half2*)h16)[2 * tid + 1] = __floats2half2_rn(v.z, v.w);
        }
        // prefetch gate-input terms (L2-resident)
        float gi[2] = {0.f, 0.f};
        if (lane == 0) {
#pragma unroll
            for (int k = 0; k < 2; ++k)
                if (k < cnt) gi[k] = g_gi[t * NGATE + rowg[k]];
        }
        __syncthreads();

        float acc[2] = {0.f, 0.f};
        const uint4*  h16u = (const uint4*)h16;
        const float4* h32f = (const float4*)h32;
#pragma unroll
        for (int i = 0; i < 8; ++i) {
            const int o = lane + 32 * i;
            uint4 hh = h16u[o];
            const __half2* hp = (const __half2*)&hh;
#pragma unroll
            for (int k = 0; k < 2; ++k) {
                if (k >= cnt) break;
                if (insm[k]) {
                    uint4 ww = wr16[k][o];
                    const __half2* wp = (const __half2*)&ww;
                    __half2 s = __hmul2(wp[0], hp[0]);
                    s = __hfma2(wp[1], hp[1], s);
                    s = __hfma2(wp[2], hp[2], s);
                    s = __hfma2(wp[3], hp[3], s);
                    float2 f = __half22float2(s);
                    acc[k] += f.x + f.y;
                } else {
                    float4 wa = __ldg(wr32[k] + 2 * o);
                    float4 wb = __ldg(wr32[k] + 2 * o + 1);
                    float4 ha = h32f[2 * o], hb = h32f[2 * o + 1];
                    acc[k] += wa.x * ha.x + wa.y * ha.y + wa.z * ha.z + wa.w * ha.w
                            + wb.x * hb.x + wb.y * hb.y + wb.z * hb.z + wb.w * hb.w;
                }
            }
        }
#pragma unroll
        for (int k = 0; k < 2; ++k)
#pragma unroll
            for (int o = 16; o > 0; o >>= 1) acc[k] += __shfl_xor_sync(0xffffffffu, acc[k], o);
        if (lane == 0) {
#pragma unroll
            for (int k = 0; k < 2; ++k)
                if (k < cnt) gsm[gsl[k]] = acc[k] + gi[k];
        }
        __syncthreads();

        if (tid < nu) {
            float ig = gsm[tid], fg = gsm[nu + tid], gg = gsm[2 * nu + tid], og = gsm[3 * nu + tid];
            float c = sigmoidf_(fg) * csm[tid] + sigmoidf_(ig) * tanhf(gg);
            float h = sigmoidf_(og) * tanhf(c);
            csm[tid] = c;
            g_h[(t + 1) & 1][u0 + tid] = h;
            out[t * H128 + u0 + tid] = h;
        }
        __syncthreads();
        if (tid == 0) st_release(&g_slot[bid * 8], (unsigned)(t + 2));
        if (tid < ncta) { unsigned tgt = (unsigned)(t + 2); while (ld_acquire(&g_slot[tid * 8]) < tgt) {} }
        __syncthreads();
    }
}

// ---------------- launch ----------------
extern "C" void kernel_launch(void* const* d_in, const int* in_sizes, int n_in,
                              void* d_out, int out_size)
{
    const float* inp  = (const float*)d_in[0];
    const float* gc1w = (const float*)d_in[3];
    const float* gc1b = (const float*)d_in[4];
    const float* gc2w = (const float*)d_in[5];
    const float* gc2b = (const float*)d_in[6];
    const float* flw  = (const float*)d_in[7];
    const float* flb  = (const float*)d_in[8];
    const float* ilw  = (const float*)d_in[9];
    const float* ilb  = (const float*)d_in[10];
    const float* olw  = (const float*)d_in[11];
    const float* olb  = (const float*)d_in[12];
    const float* wih  = (const float*)d_in[13];
    const float* whh  = (const float*)d_in[14];
    const float* bih  = (const float*)d_in[15];
    const float* bhh  = (const float*)d_in[16];
    float* out = (float*)d_out;

    int sms = 0;
    cudaDeviceGetAttribute(&sms, cudaDevAttrMultiProcessorCount, 0);
    int ncta = sms;
    if (ncta > NCTA_MAX) ncta = NCTA_MAX;
    if (ncta < 128) ncta = 128;

    cudaFuncSetAttribute(lstm_kernel, cudaFuncAttributeMaxDynamicSharedMemorySize, LSTM_SMEM);

    reset_kernel<<<1, 256>>>();                                           // idx 0
    gcn_kernel<<<BB, NN>>>(inp, gc1w, gc1b, gc2w, gc2b);                  // idx 1
    mlp_kernel<<<ncta, 256>>>(flw, flb, ilw, ilb, olw, olb,
                              wih, bih, bhh, ncta);                       // idx 2
    lstm_kernel<<<ncta, 1024, LSTM_SMEM>>>(whh, out, ncta);               // idx 3 -> ncu
}

// round 8
// speedup vs baseline: 1.2061x; 1.2061x over previous
#include <cuda_runtime.h>
#include <cuda_fp16.h>
#include <math.h>

// ---------------- problem dims ----------------
#define BB    64
#define NN    1024
#define H16   256
#define H64   1024
#define H128  2048
#define NGATE 8192

#define NCTA_MAX 148
#define USM 13                                   // units whose fp16 weights live in SMEM
// dynamic SMEM layout for lstm kernel
#define WSM_BYTES (USM * 4 * 2048 * 2)           // 212992
#define OFF_H16   (WSM_BYTES)                    // fp16 h copy   (4096 B)
#define OFF_G     (OFF_H16 + H128 * 2)           // gate preacts  (256 B)
#define OFF_C     (OFF_G + 64 * 4)               // cell state    (64 B)
#define LSTM_SMEM (OFF_C + 64)                   // 217408 B

// ---------------- device scratch ----------------
__device__ __align__(16) float g_x [BB * NN];
__device__ __align__(16) float g_af[BB * H16];
__device__ __align__(16) float g_ai[BB * H64];
__device__ __align__(16) float g_z [BB * H128];
__device__ __align__(16) float g_gi[BB * NGATE];
__device__ __align__(16) float g_part[1 << 21];      // split-K partials (8MB)
__device__ __align__(16) float g_h [2][H128];
__device__ unsigned g_slot[NCTA_MAX * 8];            // spread barrier slots (32B apart)

__global__ void reset_kernel() {
    for (int i = threadIdx.x; i < NCTA_MAX * 8; i += blockDim.x) g_slot[i] = 0u;
}

// ---------------- release/acquire helpers ----------------
__device__ __forceinline__ void st_release(unsigned* p, unsigned v) {
    asm volatile("st.release.gpu.global.u32 [%0], %1;" :: "l"(p), "r"(v) : "memory");
}
__device__ __forceinline__ unsigned ld_acquire(const unsigned* p) {
    unsigned v;
    asm volatile("ld.acquire.gpu.global.u32 %0, [%1];" : "=r"(v) : "l"(p) : "memory");
    return v;
}

// ---------------- GCN: one block per sample ----------------
__global__ __launch_bounds__(1024) void gcn_kernel(
    const float* __restrict__ inp,
    const float* __restrict__ gc1w, const float* __restrict__ gc1b,
    const float* __restrict__ gc2w, const float* __restrict__ gc2b)
{
    __shared__ float xs[NN];
    __shared__ float s2[NN];
    const int s = blockIdx.x;
    const int i = threadIdx.x;
    xs[i] = inp[s * NN + i];
    __syncthreads();
    const float xi = xs[i];

    float d0 = INFINITY, d1 = INFINITY, d2 = INFINITY, d3 = INFINITY;
    int i0 = 0, i1 = 0, i2 = 0, i3 = 0;
#pragma unroll 4
    for (int j = 0; j < NN; ++j) {
        float dj = fabsf(xi - xs[j]);
        if (j != i && dj < d3) {
            if (dj < d2) {
                d3 = d2; i3 = i2;
                if (dj < d1) {
                    d2 = d1; i2 = i1;
                    if (dj < d0) { d1 = d0; i1 = i0; d0 = dj; i0 = j; }
                    else         { d1 = dj; i1 = j; }
                } else { d2 = dj; i2 = j; }
            } else { d3 = dj; i3 = j; }
        }
    }

    float S = xs[i0] + xs[i1] + xs[i2] + xs[i3];
    float v = 0.f;
#pragma unroll
    for (int c = 0; c < 4; ++c) {
        float hc = fmaxf(gc1w[c] * S + gc1b[c], 0.f);
        v += hc * gc2w[c];
    }
    s2[i] = v;
    __syncthreads();
    g_x[s * NN + i] = s2[i0] + s2[i1] + s2[i2] + s2[i3] + gc2b[0];
}

// ---------------- small split-K GEMM (64xR', 128 thr) for fl/il ----------------
template <int R, int J, int KC>
__global__ __launch_bounds__(128) void gemm_sk(
    const float* __restrict__ A, const float* __restrict__ W, float* __restrict__ part)
{
    __shared__ float As[64][33];
    __shared__ float Ws[32][33];
    const int JC  = J / KC;
    const int kc  = blockIdx.y;
    const int br0 = blockIdx.x * 32;
    const int tid = threadIdx.x;
    const int tq  = tid & 15;
    const int rq  = tid >> 4;

    float acc[4][4];
#pragma unroll
    for (int a = 0; a < 4; ++a)
#pragma unroll
        for (int b = 0; b < 4; ++b) acc[a][b] = 0.f;

    const int j_end = (kc + 1) * JC;
    for (int j0 = kc * JC; j0 < j_end; j0 += 32) {
        for (int idx = tid; idx < 64 * 32; idx += 128) {
            int row = idx >> 5, col = idx & 31;
            As[row][col] = A[row * J + j0 + col];
        }
        for (int idx = tid; idx < 32 * 32; idx += 128) {
            int row = idx >> 5, col = idx & 31;
            Ws[row][col] = W[(size_t)(br0 + row) * J + j0 + col];
        }
        __syncthreads();
#pragma unroll
        for (int kk = 0; kk < 32; ++kk) {
            float av[4], wv[4];
#pragma unroll
            for (int a = 0; a < 4; ++a) av[a] = As[tq + 16 * a][kk];
#pragma unroll
            for (int b = 0; b < 4; ++b) wv[b] = Ws[rq + 8 * b][kk];
#pragma unroll
            for (int a = 0; a < 4; ++a)
#pragma unroll
                for (int b = 0; b < 4; ++b) acc[a][b] += av[a] * wv[b];
        }
        __syncthreads();
    }
#pragma unroll
    for (int a = 0; a < 4; ++a)
#pragma unroll
        for (int b = 0; b < 4; ++b)
            part[(size_t)kc * 64 * R + (tq + 16 * a) * R + br0 + rq + 8 * b] = acc[a][b];
}

// ---------------- big split-K GEMM: 64x64 tile, 256 thr, double-buffered ----------------
template <int R, int J, int KC>
__global__ __launch_bounds__(256) void gemm64(
    const float* __restrict__ A, const float* __restrict__ W, float* __restrict__ part)
{
    __shared__ float As[2][64][33];
    __shared__ float Ws[2][64][33];
    const int JC  = J / KC;
    const int kc  = blockIdx.y;
    const int br0 = blockIdx.x * 64;
    const int tid = threadIdx.x;
    const int tq  = tid & 15;
    const int rq  = tid >> 4;

    float acc[4][4];
#pragma unroll
    for (int a = 0; a < 4; ++a)
#pragma unroll
        for (int b = 0; b < 4; ++b) acc[a][b] = 0.f;

    const int jbeg = kc * JC;
    const int nit  = JC / 32;

    auto load = [&](int s, int j0) {
#pragma unroll
        for (int idx = tid; idx < 64 * 32; idx += 256) {
            int row = idx >> 5, col = idx & 31;
            As[s][row][col] = A[row * J + j0 + col];
            Ws[s][row][col] = W[(size_t)(br0 + row) * J + j0 + col];
        }
    };

    load(0, jbeg);
    __syncthreads();
    for (int it = 0; it < nit; ++it) {
        int s = it & 1;
        if (it + 1 < nit) load(s ^ 1, jbeg + (it + 1) * 32);
#pragma unroll
        for (int kk = 0; kk < 32; ++kk) {
            float av[4], wv[4];
#pragma unroll
            for (int a = 0; a < 4; ++a) av[a] = As[s][tq + 16 * a][kk];
#pragma unroll
            for (int b = 0; b < 4; ++b) wv[b] = Ws[s][rq + 16 * b][kk];
#pragma unroll
            for (int a = 0; a < 4; ++a)
#pragma unroll
                for (int b = 0; b < 4; ++b) acc[a][b] += av[a] * wv[b];
        }
        __syncthreads();
    }
#pragma unroll
    for (int a = 0; a < 4; ++a)
#pragma unroll
        for (int b = 0; b < 4; ++b)
            part[(size_t)kc * 64 * R + (tq + 16 * a) * R + br0 + rq + 16 * b] = acc[a][b];
}

// ---------------- reduce partials ----------------
template <int R, int KC, bool RELU, bool HASB2>
__global__ __launch_bounds__(256) void reduce_k(
    const float* __restrict__ part,
    const float* __restrict__ b1, const float* __restrict__ b2,
    float* __restrict__ C)
{
    int i = blockIdx.x * 256 + threadIdx.x;
    if (i >= 64 * R) return;
    int r = i % R;
    float s = 0.f;
#pragma unroll
    for (int kc = 0; kc < KC; ++kc) s += part[(size_t)kc * 64 * R + i];
    s += b1[r];
    if (HASB2) s += b2[r];
    if (RELU) s = fmaxf(s, 0.f);
    C[i] = s;
}

__device__ __forceinline__ float sigmoidf_(float x) { return 1.f / (1.f + expf(-x)); }

// ---------------- persistent LSTM: SMEM fp16 weights, lean HFMA2 inner loop ----------------
__global__ __launch_bounds__(1024, 1) void lstm_kernel(
    const float* __restrict__ w_hh, float* __restrict__ out, int ncta)
{
    extern __shared__ unsigned char sm[];
    __half* w_sm = (__half*)sm;                     // [4*usm][2048] fp16
    __half* h16  = (__half*)(sm + OFF_H16);         // [2048]
    float*  gsm  = (float*)(sm + OFF_G);            // [64]
    float*  csm  = (float*)(sm + OFF_C);            // [16]

    const int tid  = threadIdx.x;
    const int bid  = blockIdx.x;
    const int warp = tid >> 5, lane = tid & 31;

    const int base = H128 / ncta;
    const int rem  = H128 - base * ncta;
    const int nu   = (bid < rem) ? base + 1 : base;
    const int u0   = bid * base + min(bid, rem);
    const int usm  = (nu < USM) ? nu : USM;
    const int nrows = 4 * nu;

    // prologue: convert this CTA's SMEM-resident rows fp32 -> fp16 (once per launch)
    {
        const int tot2 = usm * 4 * 1024;
        __half2* dst = (__half2*)w_sm;
        for (int idx = tid; idx < tot2; idx += 1024) {
            int sr = idx >> 10, c2 = idx & 1023;
            int g = sr / usm, ui = sr - g * usm;
            const float2* src = (const float2*)(w_hh + (size_t)(g * H128 + u0 + ui) * H128);
            float2 v = src[c2];
            dst[idx] = __floats2half2_rn(v.x, v.y);
        }
    }

    // per-warp row assignment: lr = warp + 32*k (cnt uniform per warp)
    int cnt = 0;
    int rowg[2], gsl[2];
    bool insm[2];
    const uint4*  wr16[2];
    const float4* wr32[2];
#pragma unroll
    for (int k = 0; k < 2; ++k) {
        int lr = warp + 32 * k;
        if (lr < nrows) {
            int g = lr / nu, ui = lr - g * nu;
            rowg[cnt] = g * H128 + u0 + ui;
            gsl [cnt] = lr;
            insm[cnt] = (ui < usm);
            wr16[cnt] = (const uint4*)(w_sm + (size_t)(g * usm + ui) * H128);
            wr32[cnt] = (const float4*)(w_hh + (size_t)rowg[cnt] * H128);
            ++cnt;
        }
    }

    if (tid < nu) { csm[tid] = 0.f; g_h[0][u0 + tid] = 0.f; }
    __syncthreads();
    if (tid == 0) st_release(&g_slot[bid * 8], 1u);
    if (tid < ncta) { while (ld_acquire(&g_slot[tid * 8]) < 1u) {} }
    __syncthreads();

    for (int t = 0; t < BB; ++t) {
        // broadcast h into SMEM (fp16 only)
        if (tid < H128 / 4) {
            float4 v = __ldcg(&((const float4*)g_h[t & 1])[tid]);
            ((__half2*)h16)[2 * tid]     = __floats2half2_rn(v.x, v.y);
            ((__half2*)h16)[2 * tid + 1] = __floats2half2_rn(v.z, v.w);
        }
        // prefetch gate-input terms (L2-resident)
        float gi[2] = {0.f, 0.f};
        if (lane == 0) {
#pragma unroll
            for (int k = 0; k < 2; ++k)
                if (k < cnt) gi[k] = g_gi[t * NGATE + rowg[k]];
        }
        __syncthreads();

        float acc[2] = {0.f, 0.f};
        const uint4* h16u = (const uint4*)h16;
#pragma unroll
        for (int ii = 0; ii < 4; ++ii) {
            const int o = lane + 64 * ii;
            uint4 ha = h16u[o], hb = h16u[o + 32];
            const __half2* hpa = (const __half2*)&ha;
            const __half2* hpb = (const __half2*)&hb;
#pragma unroll
            for (int k = 0; k < 2; ++k) {
                if (k >= cnt) break;                 // warp-uniform branch
                __half2 s;
                if (insm[k]) {
                    uint4 wa = wr16[k][o], wb = wr16[k][o + 32];
                    const __half2* wpa = (const __half2*)&wa;
                    const __half2* wpb = (const __half2*)&wb;
                    s = __hmul2(wpa[0], hpa[0]);
                    s = __hfma2(wpa[1], hpa[1], s);
                    s = __hfma2(wpa[2], hpa[2], s);
                    s = __hfma2(wpa[3], hpa[3], s);
                    s = __hfma2(wpb[0], hpb[0], s);
                    s = __hfma2(wpb[1], hpb[1], s);
                    s = __hfma2(wpb[2], hpb[2], s);
                    s = __hfma2(wpb[3], hpb[3], s);
                } else {
                    float4 a0 = __ldg(wr32[k] + 2 * o);
                    float4 a1 = __ldg(wr32[k] + 2 * o + 1);
                    float4 b0 = __ldg(wr32[k] + 2 * (o + 32));
                    float4 b1 = __ldg(wr32[k] + 2 * (o + 32) + 1);
                    s = __hmul2(__floats2half2_rn(a0.x, a0.y), hpa[0]);
                    s = __hfma2(__floats2half2_rn(a0.z, a0.w), hpa[1], s);
                    s = __hfma2(__floats2half2_rn(a1.x, a1.y), hpa[2], s);
                    s = __hfma2(__floats2half2_rn(a1.z, a1.w), hpa[3], s);
                    s = __hfma2(__floats2half2_rn(b0.x, b0.y), hpb[0], s);
                    s = __hfma2(__floats2half2_rn(b0.z, b0.w), hpb[1], s);
                    s = __hfma2(__floats2half2_rn(b1.x, b1.y), hpb[2], s);
                    s = __hfma2(__floats2half2_rn(b1.z, b1.w), hpb[3], s);
                }
                float2 f = __half22float2(s);
                acc[k] += f.x + f.y;
            }
        }
#pragma unroll
        for (int k = 0; k < 2; ++k)
#pragma unroll
            for (int o = 16; o > 0; o >>= 1) acc[k] += __shfl_xor_sync(0xffffffffu, acc[k], o);
        if (lane == 0) {
#pragma unroll
            for (int k = 0; k < 2; ++k)
                if (k < cnt) gsm[gsl[k]] = acc[k] + gi[k];
        }
        __syncthreads();

        if (tid < nu) {
            float ig = gsm[tid], fg = gsm[nu + tid], gg = gsm[2 * nu + tid], og = gsm[3 * nu + tid];
            float c = sigmoidf_(fg) * csm[tid] + sigmoidf_(ig) * tanhf(gg);
            float h = sigmoidf_(og) * tanhf(c);
            csm[tid] = c;
            g_h[(t + 1) & 1][u0 + tid] = h;
            out[t * H128 + u0 + tid] = h;
        }
        __syncthreads();
        if (tid == 0) st_release(&g_slot[bid * 8], (unsigned)(t + 2));
        if (tid < ncta) { unsigned tgt = (unsigned)(t + 2); while (ld_acquire(&g_slot[tid * 8]) < tgt) {} }
        __syncthreads();
    }
}

// ---------------- launch ----------------
extern "C" void kernel_launch(void* const* d_in, const int* in_sizes, int n_in,
                              void* d_out, int out_size)
{
    const float* inp  = (const float*)d_in[0];
    const float* gc1w = (const float*)d_in[3];
    const float* gc1b = (const float*)d_in[4];
    const float* gc2w = (const float*)d_in[5];
    const float* gc2b = (const float*)d_in[6];
    const float* flw  = (const float*)d_in[7];
    const float* flb  = (const float*)d_in[8];
    const float* ilw  = (const float*)d_in[9];
    const float* ilb  = (const float*)d_in[10];
    const float* olw  = (const float*)d_in[11];
    const float* olb  = (const float*)d_in[12];
    const float* wih  = (const float*)d_in[13];
    const float* whh  = (const float*)d_in[14];
    const float* bih  = (const float*)d_in[15];
    const float* bhh  = (const float*)d_in[16];
    float* out = (float*)d_out;

    void *px, *paf, *pai, *pz, *pgi, *ppart;
    cudaGetSymbolAddress(&px,    g_x);
    cudaGetSymbolAddress(&paf,   g_af);
    cudaGetSymbolAddress(&pai,   g_ai);
    cudaGetSymbolAddress(&pz,    g_z);
    cudaGetSymbolAddress(&pgi,   g_gi);
    cudaGetSymbolAddress(&ppart, g_part);
    float* part = (float*)ppart;

    int sms = 0;
    cudaDeviceGetAttribute(&sms, cudaDevAttrMultiProcessorCount, 0);
    int ncta = sms;
    if (ncta > NCTA_MAX) ncta = NCTA_MAX;
    if (ncta < 128) ncta = 128;

    cudaFuncSetAttribute(lstm_kernel, cudaFuncAttributeMaxDynamicSharedMemorySize, LSTM_SMEM);

    reset_kernel<<<1, 256>>>();
    gcn_kernel<<<BB, NN>>>(inp, gc1w, gc1b, gc2w, gc2b);

    // fl: [64,256] = x @ fl_w.T ; relu
    gemm_sk<H16, NN, 16><<<dim3(H16 / 32, 16), 128>>>((const float*)px, flw, part);
    reduce_k<H16, 16, true, false><<<(64 * H16 + 255) / 256, 256>>>(part, flb, nullptr, (float*)paf);
    // il: [64,1024] = af @ il_w.T ; relu
    gemm_sk<H64, H16, 4><<<dim3(H64 / 32, 4), 128>>>((const float*)paf, ilw, part);
    reduce_k<H64, 4, true, false><<<(64 * H64 + 255) / 256, 256>>>(part, ilb, nullptr, (float*)pai);
    // ol: [64,2048] = ai @ ol_w.T ; relu -> z
    gemm64<H128, H64, 4><<<dim3(H128 / 64, 4), 256>>>((const float*)pai, olw, part);
    reduce_k<H128, 4, true, false><<<(64 * H128 + 255) / 256, 256>>>(part, olb, nullptr, (float*)pz);
    // gate: [64,8192] = z @ w_ih.T + b_ih + b_hh
    gemm64<NGATE, H128, 4><<<dim3(NGATE / 64, 4), 256>>>((const float*)pz, wih, part);
    reduce_k<NGATE, 4, false, true><<<(64 * NGATE + 255) / 256, 256>>>(part, bih, bhh, (float*)pgi);

    lstm_kernel<<<ncta, 1024, LSTM_SMEM>>>(whh, out, ncta);
}

// round 9
// speedup vs baseline: 1.2789x; 1.0603x over previous
#include <cuda_runtime.h>
#include <cuda_fp16.h>
#include <math.h>

// ---------------- problem dims ----------------
#define BB    64
#define NN    1024
#define H16   256
#define H64   1024
#define H128  2048
#define NGATE 8192

#define NCTA_MAX 148
#define WROWS 55                                 // gate rows resident in SMEM per CTA
// dynamic SMEM layout for lstm kernel
#define OFF_H16   (WROWS * 2048 * 2)             // 225280: fp16 h copy (4096 B)
#define OFF_G     (OFF_H16 + H128 * 2)           // gate preacts  (256 B)
#define OFF_C     (OFF_G + 64 * 4)               // cell state    (64 B)
#define LSTM_SMEM (OFF_C + 64)                   // 229696 B (<= 232448 max)

// ---------------- device scratch ----------------
__device__ __align__(16) float  g_x [BB * NN];
__device__ __align__(16) float  g_af[BB * H16];
__device__ __align__(16) float  g_ai[BB * H64];
__device__ __align__(16) float  g_z [BB * H128];
__device__ __align__(16) __half g_z16[BB * H128];
__device__ __align__(16) float  g_gi[BB * NGATE];
__device__ __align__(16) float  g_part[1 << 21];     // split-K partials (8MB)
__device__ __align__(16) float  g_h [2][H128];
__device__ unsigned g_slot[NCTA_MAX * 8];            // spread barrier slots (32B apart)

__global__ void reset_kernel() {
    for (int i = threadIdx.x; i < NCTA_MAX * 8; i += blockDim.x) g_slot[i] = 0u;
}

// ---------------- release/acquire helpers ----------------
__device__ __forceinline__ void st_release(unsigned* p, unsigned v) {
    asm volatile("st.release.gpu.global.u32 [%0], %1;" :: "l"(p), "r"(v) : "memory");
}
__device__ __forceinline__ unsigned ld_acquire(const unsigned* p) {
    unsigned v;
    asm volatile("ld.acquire.gpu.global.u32 %0, [%1];" : "=r"(v) : "l"(p) : "memory");
    return v;
}

// ---------------- GCN: one block per sample ----------------
__global__ __launch_bounds__(1024) void gcn_kernel(
    const float* __restrict__ inp,
    const float* __restrict__ gc1w, const float* __restrict__ gc1b,
    const float* __restrict__ gc2w, const float* __restrict__ gc2b)
{
    __shared__ float xs[NN];
    __shared__ float s2[NN];
    const int s = blockIdx.x;
    const int i = threadIdx.x;
    xs[i] = inp[s * NN + i];
    __syncthreads();
    const float xi = xs[i];

    float d0 = INFINITY, d1 = INFINITY, d2 = INFINITY, d3 = INFINITY;
    int i0 = 0, i1 = 0, i2 = 0, i3 = 0;
#pragma unroll 4
    for (int j = 0; j < NN; ++j) {
        float dj = fabsf(xi - xs[j]);
        if (j != i && dj < d3) {
            if (dj < d2) {
                d3 = d2; i3 = i2;
                if (dj < d1) {
                    d2 = d1; i2 = i1;
                    if (dj < d0) { d1 = d0; i1 = i0; d0 = dj; i0 = j; }
                    else         { d1 = dj; i1 = j; }
                } else { d2 = dj; i2 = j; }
            } else { d3 = dj; i3 = j; }
        }
    }

    float S = xs[i0] + xs[i1] + xs[i2] + xs[i3];
    float v = 0.f;
#pragma unroll
    for (int c = 0; c < 4; ++c) {
        float hc = fmaxf(gc1w[c] * S + gc1b[c], 0.f);
        v += hc * gc2w[c];
    }
    s2[i] = v;
    __syncthreads();
    g_x[s * NN + i] = s2[i0] + s2[i1] + s2[i2] + s2[i3] + gc2b[0];
}

// ---------------- small split-K GEMM (64xR', 128 thr) for fl/il ----------------
template <int R, int J, int KC>
__global__ __launch_bounds__(128) void gemm_sk(
    const float* __restrict__ A, const float* __restrict__ W, float* __restrict__ part)
{
    __shared__ float As[64][33];
    __shared__ float Ws[32][33];
    const int JC  = J / KC;
    const int kc  = blockIdx.y;
    const int br0 = blockIdx.x * 32;
    const int tid = threadIdx.x;
    const int tq  = tid & 15;
    const int rq  = tid >> 4;

    float acc[4][4];
#pragma unroll
    for (int a = 0; a < 4; ++a)
#pragma unroll
        for (int b = 0; b < 4; ++b) acc[a][b] = 0.f;

    const int j_end = (kc + 1) * JC;
    for (int j0 = kc * JC; j0 < j_end; j0 += 32) {
        for (int idx = tid; idx < 64 * 32; idx += 128) {
            int row = idx >> 5, col = idx & 31;
            As[row][col] = A[row * J + j0 + col];
        }
        for (int idx = tid; idx < 32 * 32; idx += 128) {
            int row = idx >> 5, col = idx & 31;
            Ws[row][col] = W[(size_t)(br0 + row) * J + j0 + col];
        }
        __syncthreads();
#pragma unroll
        for (int kk = 0; kk < 32; ++kk) {
            float av[4], wv[4];
#pragma unroll
            for (int a = 0; a < 4; ++a) av[a] = As[tq + 16 * a][kk];
#pragma unroll
            for (int b = 0; b < 4; ++b) wv[b] = Ws[rq + 8 * b][kk];
#pragma unroll
            for (int a = 0; a < 4; ++a)
#pragma unroll
                for (int b = 0; b < 4; ++b) acc[a][b] += av[a] * wv[b];
        }
        __syncthreads();
    }
#pragma unroll
    for (int a = 0; a < 4; ++a)
#pragma unroll
        for (int b = 0; b < 4; ++b)
            part[(size_t)kc * 64 * R + (tq + 16 * a) * R + br0 + rq + 8 * b] = acc[a][b];
}

// ---------------- big split-K fp32 GEMM (ol layer): 64x64 tile, double-buffered ----------------
template <int R, int J, int KC>
__global__ __launch_bounds__(256) void gemm64(
    const float* __restrict__ A, const float* __restrict__ W, float* __restrict__ part)
{
    __shared__ float As[2][64][33];
    __shared__ float Ws[2][64][33];
    const int JC  = J / KC;
    const int kc  = blockIdx.y;
    const int br0 = blockIdx.x * 64;
    const int tid = threadIdx.x;
    const int tq  = tid & 15;
    const int rq  = tid >> 4;

    float acc[4][4];
#pragma unroll
    for (int a = 0; a < 4; ++a)
#pragma unroll
        for (int b = 0; b < 4; ++b) acc[a][b] = 0.f;

    const int jbeg = kc * JC;
    const int nit  = JC / 32;

    auto load = [&](int s, int j0) {
#pragma unroll
        for (int idx = tid; idx < 64 * 32; idx += 256) {
            int row = idx >> 5, col = idx & 31;
            As[s][row][col] = A[row * J + j0 + col];
            Ws[s][row][col] = W[(size_t)(br0 + row) * J + j0 + col];
        }
    };

    load(0, jbeg);
    __syncthreads();
    for (int it = 0; it < nit; ++it) {
        int s = it & 1;
        if (it + 1 < nit) load(s ^ 1, jbeg + (it + 1) * 32);
#pragma unroll
        for (int kk = 0; kk < 32; ++kk) {
            float av[4], wv[4];
#pragma unroll
            for (int a = 0; a < 4; ++a) av[a] = As[s][tq + 16 * a][kk];
#pragma unroll
            for (int b = 0; b < 4; ++b) wv[b] = Ws[s][rq + 16 * b][kk];
#pragma unroll
            for (int a = 0; a < 4; ++a)
#pragma unroll
                for (int b = 0; b < 4; ++b) acc[a][b] += av[a] * wv[b];
        }
        __syncthreads();
    }
#pragma unroll
    for (int a = 0; a < 4; ++a)
#pragma unroll
        for (int b = 0; b < 4; ++b)
            part[(size_t)kc * 64 * R + (tq + 16 * a) * R + br0 + rq + 16 * b] = acc[a][b];
}

// ---------------- z fp32 -> fp16 ----------------
__global__ __launch_bounds__(256) void convert_z()
{
    int i = blockIdx.x * 256 + threadIdx.x;          // half2 index, 64*2048/2 = 65536
    if (i >= BB * H128 / 2) return;
    float2 v = ((const float2*)g_z)[i];
    ((__half2*)g_z16)[i] = __floats2half2_rn(v.x, v.y);
}

// ---------------- gate GEMM: fp16 HFMA2, fp32 chunk-promoted accumulation ----------------
// A16 = z16 [64][J] half; W = w_ih [R][J] fp32 converted to half in the tile-load path.
template <int R, int J, int KC>
__global__ __launch_bounds__(256) void gemm64h(
    const __half* __restrict__ A16, const float* __restrict__ W,
    float* __restrict__ part)
{
    __shared__ __half2 As[2][64][17];   // 16 half2 (=32 K) + 1 pad
    __shared__ __half2 Ws[2][64][17];
    const int JC  = J / KC;
    const int kc  = blockIdx.y;
    const int br0 = blockIdx.x * 64;
    const int tid = threadIdx.x;
    const int tq  = tid & 15;
    const int rq  = tid >> 4;

    float acc[4][4];
#pragma unroll
    for (int a = 0; a < 4; ++a)
#pragma unroll
        for (int b = 0; b < 4; ++b) acc[a][b] = 0.f;

    const int jbeg = kc * JC;
    const int nit  = JC / 32;
    const int row  = tid >> 2;          // 0..63
    const int c4   = tid & 3;           // 16B chunk within 32-half row slice

    auto load = [&](int s, int j0) {
        // A: 64 rows x 4 uint4 (32 halfs); one uint4 per thread
        {
            uint4 v = *((const uint4*)(A16 + row * J + j0) + c4);
            const __half2* pv = (const __half2*)&v;
            __half2* d = &As[s][row][c4 * 4];
            d[0] = pv[0]; d[1] = pv[1]; d[2] = pv[2]; d[3] = pv[3];
        }
        // W: 64 rows x 32 floats; 8 floats per thread, converted to half2
        {
            const float4* src = (const float4*)(W + (size_t)(br0 + row) * J + j0) + c4 * 2;
            float4 a = src[0], b = src[1];
            __half2* d = &Ws[s][row][c4 * 4];
            d[0] = __floats2half2_rn(a.x, a.y);
            d[1] = __floats2half2_rn(a.z, a.w);
            d[2] = __floats2half2_rn(b.x, b.y);
            d[3] = __floats2half2_rn(b.z, b.w);
        }
    };

    load(0, jbeg);
    __syncthreads();
    for (int it = 0; it < nit; ++it) {
        int s = it & 1;
        if (it + 1 < nit) load(s ^ 1, jbeg + (it + 1) * 32);
        __half2 h2[4][4];
        {
            __half2 av[4], wv[4];
#pragma unroll
            for (int a = 0; a < 4; ++a) av[a] = As[s][tq + 16 * a][0];
#pragma unroll
            for (int b = 0; b < 4; ++b) wv[b] = Ws[s][rq + 16 * b][0];
#pragma unroll
            for (int a = 0; a < 4; ++a)
#pragma unroll
                for (int b = 0; b < 4; ++b) h2[a][b] = __hmul2(av[a], wv[b]);
        }
#pragma unroll
        for (int kk = 1; kk < 16; ++kk) {
            __half2 av[4], wv[4];
#pragma unroll
            for (int a = 0; a < 4; ++a) av[a] = As[s][tq + 16 * a][kk];
#pragma unroll
            for (int b = 0; b < 4; ++b) wv[b] = Ws[s][rq + 16 * b][kk];
#pragma unroll
            for (int a = 0; a < 4; ++a)
#pragma unroll
                for (int b = 0; b < 4; ++b) h2[a][b] = __hfma2(av[a], wv[b], h2[a][b]);
        }
#pragma unroll
        for (int a = 0; a < 4; ++a)
#pragma unroll
            for (int b = 0; b < 4; ++b) {
                float2 f = __half22float2(h2[a][b]);
                acc[a][b] += f.x + f.y;
            }
        __syncthreads();
    }
#pragma unroll
    for (int a = 0; a < 4; ++a)
#pragma unroll
        for (int b = 0; b < 4; ++b)
            part[(size_t)kc * 64 * R + (tq + 16 * a) * R + br0 + rq + 16 * b] = acc[a][b];
}

// ---------------- reduce partials ----------------
template <int R, int KC, bool RELU, bool HASB2>
__global__ __launch_bounds__(256) void reduce_k(
    const float* __restrict__ part,
    const float* __restrict__ b1, const float* __restrict__ b2,
    float* __restrict__ C)
{
    int i = blockIdx.x * 256 + threadIdx.x;
    if (i >= 64 * R) return;
    int r = i % R;
    float s = 0.f;
#pragma unroll
    for (int kc = 0; kc < KC; ++kc) s += part[(size_t)kc * 64 * R + i];
    s += b1[r];
    if (HASB2) s += b2[r];
    if (RELU) s = fmaxf(s, 0.f);
    C[i] = s;
}

__device__ __forceinline__ float sigmoidf_(float x) { return 1.f / (1.f + expf(-x)); }

// ---------------- persistent LSTM: 55 SMEM rows, lean HFMA2 inner loop ----------------
__global__ __launch_bounds__(1024, 1) void lstm_kernel(
    const float* __restrict__ w_hh, float* __restrict__ out, int ncta)
{
    extern __shared__ unsigned char sm[];
    __half* w_sm = (__half*)sm;                     // [WROWS][2048] fp16, row = lr
    __half* h16  = (__half*)(sm + OFF_H16);         // [2048]
    float*  gsm  = (float*)(sm + OFF_G);            // [64]
    float*  csm  = (float*)(sm + OFF_C);            // [16]

    const int tid  = threadIdx.x;
    const int bid  = blockIdx.x;
    const int warp = tid >> 5, lane = tid & 31;

    const int base = H128 / ncta;
    const int rem  = H128 - base * ncta;
    const int nu   = (bid < rem) ? base + 1 : base;
    const int u0   = bid * base + min(bid, rem);
    const int nrows = 4 * nu;
    const int wrows = (nrows < WROWS) ? nrows : WROWS;   // rows resident in SMEM

    // prologue: convert resident rows fp32 -> fp16, SMEM row index = lr
    {
        const int tot2 = wrows * 1024;              // half2 count
        __half2* dst = (__half2*)w_sm;
        for (int idx = tid; idx < tot2; idx += 1024) {
            int lr = idx >> 10, c2 = idx & 1023;
            int g = lr / nu, ui = lr - g * nu;
            const float2* src = (const float2*)(w_hh + (size_t)(g * H128 + u0 + ui) * H128);
            float2 v = src[c2];
            dst[idx] = __floats2half2_rn(v.x, v.y);
        }
    }

    // per-warp row assignment: lr = warp + 32*k (cnt uniform per warp)
    int cnt = 0;
    int rowg[2], gsl[2];
    bool insm[2];
    const uint4*  wr16[2];
    const float4* wr32[2];
#pragma unroll
    for (int k = 0; k < 2; ++k) {
        int lr = warp + 32 * k;
        if (lr < nrows) {
            int g = lr / nu, ui = lr - g * nu;
            rowg[cnt] = g * H128 + u0 + ui;
            gsl [cnt] = lr;
            insm[cnt] = (lr < wrows);
            wr16[cnt] = (const uint4*)(w_sm + (size_t)lr * H128);
            wr32[cnt] = (const float4*)(w_hh + (size_t)rowg[cnt] * H128);
            ++cnt;
        }
    }

    if (tid < nu) { csm[tid] = 0.f; g_h[0][u0 + tid] = 0.f; }
    __syncthreads();
    if (tid == 0) st_release(&g_slot[bid * 8], 1u);
    if (tid < ncta) { while (ld_acquire(&g_slot[tid * 8]) < 1u) {} }
    __syncthreads();

    for (int t = 0; t < BB; ++t) {
        // broadcast h into SMEM (fp16 only)
        if (tid < H128 / 4) {
            float4 v = __ldcg(&((const float4*)g_h[t & 1])[tid]);
            ((__half2*)h16)[2 * tid]     = __floats2half2_rn(v.x, v.y);
            ((__half2*)h16)[2 * tid + 1] = __floats2half2_rn(v.z, v.w);
        }
        // prefetch gate-input terms (L2-resident)
        float gi[2] = {0.f, 0.f};
        if (lane == 0) {
#pragma unroll
            for (int k = 0; k < 2; ++k)
                if (k < cnt) gi[k] = g_gi[t * NGATE + rowg[k]];
        }
        __syncthreads();

        float acc[2] = {0.f, 0.f};
        const uint4* h16u = (const uint4*)h16;
#pragma unroll
        for (int ii = 0; ii < 4; ++ii) {
            const int o = lane + 64 * ii;
            uint4 ha = h16u[o], hb = h16u[o + 32];
            const __half2* hpa = (const __half2*)&ha;
            const __half2* hpb = (const __half2*)&hb;
#pragma unroll
            for (int k = 0; k < 2; ++k) {
                if (k >= cnt) break;                 // warp-uniform branch
                __half2 s;
                if (insm[k]) {
                    uint4 wa = wr16[k][o], wb = wr16[k][o + 32];
                    const __half2* wpa = (const __half2*)&wa;
                    const __half2* wpb = (const __half2*)&wb;
                    s = __hmul2(wpa[0], hpa[0]);
                    s = __hfma2(wpa[1], hpa[1], s);
                    s = __hfma2(wpa[2], hpa[2], s);
                    s = __hfma2(wpa[3], hpa[3], s);
                    s = __hfma2(wpb[0], hpb[0], s);
                    s = __hfma2(wpb[1], hpb[1], s);
                    s = __hfma2(wpb[2], hpb[2], s);
                    s = __hfma2(wpb[3], hpb[3], s);
                } else {
                    float4 a0 = __ldg(wr32[k] + 2 * o);
                    float4 a1 = __ldg(wr32[k] + 2 * o + 1);
                    float4 b0 = __ldg(wr32[k] + 2 * (o + 32));
                    float4 b1 = __ldg(wr32[k] + 2 * (o + 32) + 1);
                    s = __hmul2(__floats2half2_rn(a0.x, a0.y), hpa[0]);
                    s = __hfma2(__floats2half2_rn(a0.z, a0.w), hpa[1], s);
                    s = __hfma2(__floats2half2_rn(a1.x, a1.y), hpa[2], s);
                    s = __hfma2(__floats2half2_rn(a1.z, a1.w), hpa[3], s);
                    s = __hfma2(__floats2half2_rn(b0.x, b0.y), hpb[0], s);
                    s = __hfma2(__floats2half2_rn(b0.z, b0.w), hpb[1], s);
                    s = __hfma2(__floats2half2_rn(b1.x, b1.y), hpb[2], s);
                    s = __hfma2(__floats2half2_rn(b1.z, b1.w), hpb[3], s);
                }
                float2 f = __half22float2(s);
                acc[k] += f.x + f.y;
            }
        }
#pragma unroll
        for (int k = 0; k < 2; ++k)
#pragma unroll
            for (int o = 16; o > 0; o >>= 1) acc[k] += __shfl_xor_sync(0xffffffffu, acc[k], o);
        if (lane == 0) {
#pragma unroll
            for (int k = 0; k < 2; ++k)
                if (k < cnt) gsm[gsl[k]] = acc[k] + gi[k];
        }
        __syncthreads();

        if (tid < nu) {
            float ig = gsm[tid], fg = gsm[nu + tid], gg = gsm[2 * nu + tid], og = gsm[3 * nu + tid];
            float c = sigmoidf_(fg) * csm[tid] + sigmoidf_(ig) * tanhf(gg);
            float h = sigmoidf_(og) * tanhf(c);
            csm[tid] = c;
            g_h[(t + 1) & 1][u0 + tid] = h;
            out[t * H128 + u0 + tid] = h;
        }
        __syncthreads();
        if (tid == 0) st_release(&g_slot[bid * 8], (unsigned)(t + 2));
        if (tid < ncta) { unsigned tgt = (unsigned)(t + 2); while (ld_acquire(&g_slot[tid * 8]) < tgt) {} }
        __syncthreads();
    }
}

// ---------------- launch ----------------
extern "C" void kernel_launch(void* const* d_in, const int* in_sizes, int n_in,
                              void* d_out, int out_size)
{
    const float* inp  = (const float*)d_in[0];
    const float* gc1w = (const float*)d_in[3];
    const float* gc1b = (const float*)d_in[4];
    const float* gc2w = (const float*)d_in[5];
    const float* gc2b = (const float*)d_in[6];
    const float* flw  = (const float*)d_in[7];
    const float* flb  = (const float*)d_in[8];
    const float* ilw  = (const float*)d_in[9];
    const float* ilb  = (const float*)d_in[10];
    const float* olw  = (const float*)d_in[11];
    const float* olb  = (const float*)d_in[12];
    const float* wih  = (const float*)d_in[13];
    const float* whh  = (const float*)d_in[14];
    const float* bih  = (const float*)d_in[15];
    const float* bhh  = (const float*)d_in[16];
    float* out = (float*)d_out;

    void *px, *paf, *pai, *pz, *pz16, *pgi, *ppart;
    cudaGetSymbolAddress(&px,    g_x);
    cudaGetSymbolAddress(&paf,   g_af);
    cudaGetSymbolAddress(&pai,   g_ai);
    cudaGetSymbolAddress(&pz,    g_z);
    cudaGetSymbolAddress(&pz16,  g_z16);
    cudaGetSymbolAddress(&pgi,   g_gi);
    cudaGetSymbolAddress(&ppart, g_part);
    float* part = (float*)ppart;

    int sms = 0;
    cudaDeviceGetAttribute(&sms, cudaDevAttrMultiProcessorCount, 0);
    int ncta = sms;
    if (ncta > NCTA_MAX) ncta = NCTA_MAX;
    if (ncta < 128) ncta = 128;

    cudaFuncSetAttribute(lstm_kernel, cudaFuncAttributeMaxDynamicSharedMemorySize, LSTM_SMEM);

    reset_kernel<<<1, 256>>>();
    gcn_kernel<<<BB, NN>>>(inp, gc1w, gc1b, gc2w, gc2b);

    // fl: [64,256] = x @ fl_w.T ; relu
    gemm_sk<H16, NN, 16><<<dim3(H16 / 32, 16), 128>>>((const float*)px, flw, part);
    reduce_k<H16, 16, true, false><<<(64 * H16 + 255) / 256, 256>>>(part, flb, nullptr, (float*)paf);
    // il: [64,1024] = af @ il_w.T ; relu
    gemm_sk<H64, H16, 4><<<dim3(H64 / 32, 4), 128>>>((const float*)paf, ilw, part);
    reduce_k<H64, 4, true, false><<<(64 * H64 + 255) / 256, 256>>>(part, ilb, nullptr, (float*)pai);
    // ol: [64,2048] = ai @ ol_w.T ; relu -> z
    gemm64<H128, H64, 4><<<dim3(H128 / 64, 4), 256>>>((const float*)pai, olw, part);
    reduce_k<H128, 4, true, false><<<(64 * H128 + 255) / 256, 256>>>(part, olb, nullptr, (float*)pz);
    // z -> fp16
    convert_z<<<(BB * H128 / 2 + 255) / 256, 256>>>();
    // gate: [64,8192] = z @ w_ih.T + b_ih + b_hh   (fp16 HFMA2)
    gemm64h<NGATE, H128, 4><<<dim3(NGATE / 64, 4), 256>>>((const __half*)pz16, wih, part);
    reduce_k<NGATE, 4, false, true><<<(64 * NGATE + 255) / 256, 256>>>(part, bih, bhh, (float*)pgi);

    lstm_kernel<<<ncta, 1024, LSTM_SMEM>>>(whh, out, ncta);
}